// round 11
// baseline (speedup 1.0000x reference)
#include <cuda_runtime.h>
#include <cstdint>

#define IN_DIM   5000
#define TOPK     50
#define BATCH    16384
#define H1       32
#define H2       16
#define OUT_DIM  30

#define NBIN     4096
#define MAXCAND  512

#define RW        2                      // rows per warp
#define MLP_BLK   256                    // 8 warps
#define MLP_GRID  (BATCH / (8 * RW))     // 1024 CTAs
#define PF        16                     // rotating prefetch depth (lines)

// scratch (no allocations allowed)
__device__ int g_topk_idx[64];

static __device__ __forceinline__ unsigned key32(float f) {
    unsigned u = __float_as_uint(f);
    return (u & 0x80000000u) ? ~u : (u | 0x80000000u);  // monotonic
}

// ---------------------------------------------------------------------------
// Kernel 1: single-CTA histogram top-k -> mask + compact index list
// ---------------------------------------------------------------------------
__global__ void __launch_bounds__(1024, 1)
k_topk(const float* __restrict__ logits, float* __restrict__ mask_out) {
    __shared__ unsigned skey[IN_DIM];
    __shared__ int hist[NBIN];
    __shared__ int groupsum[128];
    __shared__ int sgrp[128];
    __shared__ int sbin[32];
    __shared__ int s_g, s_above, s_T, s_m, s_ncand;
    __shared__ int      cand_idx[MAXCAND];
    __shared__ unsigned cand_key[MAXCAND];
    __shared__ unsigned char sel[IN_DIM];
    __shared__ int wcnt[32], wbase[32];

    const int tid = threadIdx.x;
    const int w = tid >> 5, l = tid & 31;

    for (int i = tid; i < NBIN; i += 1024) hist[i] = 0;
    if (tid == 0) s_ncand = 0;
    __syncthreads();

    for (int i = tid; i < IN_DIM; i += 1024) {
        unsigned u = key32(logits[i]);
        skey[i] = u;
        atomicAdd(&hist[u >> 20], 1);
    }
    __syncthreads();

    if (tid < 128) {
        int s = 0;
#pragma unroll
        for (int j = 0; j < 32; j++) s += hist[tid * 32 + j];
        groupsum[tid] = s;
    }
    __syncthreads();
    if (tid < 128) {
        int s = 0;
        for (int g = tid; g < 128; g++) s += groupsum[g];
        sgrp[tid] = s;
    }
    __syncthreads();
    if (tid < 128) {
        const int nxt = (tid == 127) ? 0 : sgrp[tid + 1];
        if (sgrp[tid] >= TOPK && nxt < TOPK) { s_g = tid; s_above = nxt; }
    }
    __syncthreads();
    if (tid < 32) {
        const int b0 = s_g * 32;
        int s = 0;
        for (int b = b0 + tid; b < b0 + 32; b++) s += hist[b];
        sbin[tid] = s;
    }
    __syncthreads();
    if (tid < 32) {
        const int cur = sbin[tid] + s_above;
        const int nxt = (tid == 31) ? s_above : (sbin[tid + 1] + s_above);
        if (cur >= TOPK && nxt < TOPK) { s_T = s_g * 32 + tid; s_m = TOPK - nxt; }
    }
    __syncthreads();
    const int T = s_T, m = s_m;

    for (int i = tid; i < IN_DIM; i += 1024) {
        const int b = (int)(skey[i] >> 20);
        sel[i] = (b > T) ? 1 : 0;
        if (b == T) {
            int c = atomicAdd(&s_ncand, 1);
            if (c < MAXCAND) { cand_idx[c] = i; cand_key[c] = skey[i]; }
        }
    }
    __syncthreads();

    const int nc = min(s_ncand, MAXCAND);
    for (int ci = tid; ci < nc; ci += 1024) {
        const unsigned ki = cand_key[ci];
        const int      ii = cand_idx[ci];
        int rank = 0;
        for (int cj = 0; cj < nc; cj++) {
            const unsigned kj = cand_key[cj];
            rank += (kj > ki || (kj == ki && cand_idx[cj] < ii)) ? 1 : 0;
        }
        if (rank < m) sel[ii] = 1;
    }
    __syncthreads();

    if (mask_out)
        for (int i = tid; i < IN_DIM; i += 1024)
            mask_out[i] = sel[i] ? 1.0f : 0.0f;

    // parallel index-ordered compaction
    unsigned bm[5];
    int cnt = 0;
#pragma unroll
    for (int c = 0; c < 5; c++) {
        const int i = w * 160 + c * 32 + l;
        const bool s = (i < IN_DIM) && sel[i];
        bm[c] = __ballot_sync(0xffffffffu, s);
        cnt += __popc(bm[c]);
    }
    if (l == 0) wcnt[w] = cnt;
    __syncthreads();
    if (tid < 32) {
        int v = wcnt[tid];
        int inc = v;
#pragma unroll
        for (int d = 1; d < 32; d <<= 1) {
            int t = __shfl_up_sync(0xffffffffu, inc, d);
            if (tid >= d) inc += t;
        }
        wbase[tid] = inc - v;
    }
    __syncthreads();
    int base = wbase[w];
#pragma unroll
    for (int c = 0; c < 5; c++) {
        const int i = w * 160 + c * 32 + l;
        const unsigned b = bm[c];
        if ((i < IN_DIM) && sel[i])
            g_topk_idx[base + __popc(b & ((1u << l) - 1u))] = i;
        base += __popc(b);
    }
}

// ---------------------------------------------------------------------------
// Kernel 2: FULL-LINE gather (warp loads the 128B line holding column k; one
//   shfl extracts the element) with a 16-deep rotating register prefetch so
//   each warp keeps ~16 lines in flight continuously. 2 rows/warp, 8 warps,
//   grid 1024 (~28 warps/SM). PDL hides k_topk behind weight staging.
// ---------------------------------------------------------------------------
__global__ void __launch_bounds__(MLP_BLK, 3)
k_mlp(const float* __restrict__ x,
      const float* __restrict__ W1, const float* __restrict__ b1,
      const float* __restrict__ W2, const float* __restrict__ b2,
      const float* __restrict__ W3, const float* __restrict__ b3,
      float* __restrict__ out) {
    __shared__ int   sline[TOPK];     // line base (col & ~31)
    __shared__ int   ssrc[TOPK];      // shfl source lane (col & 31)
    __shared__ float sW1[TOPK * H1];  // [k][j]
    __shared__ float sW2[H1 * H2];
    __shared__ float sW3[H2 * OUT_DIM];
    __shared__ float sb1[H1], sb2[H2], sb3[OUT_DIM];
    __shared__ int   sidx_tmp[TOPK];

    const int tid  = threadIdx.x;
    const int warp = tid >> 5;
    const int lane = tid & 31;

    // ---- topk-independent weight staging overlaps k_topk (PDL) ----
    for (int t = tid; t < H1 * H2; t += MLP_BLK)      sW2[t] = W2[t];
    for (int t = tid; t < H2 * OUT_DIM; t += MLP_BLK) sW3[t] = W3[t];
    if (tid < H1)      sb1[tid] = b1[tid];
    if (tid < H2)      sb2[tid] = b2[tid];
    if (tid < OUT_DIM) sb3[tid] = b3[tid];

#if __CUDA_ARCH__ >= 900
    cudaGridDependencySynchronize();
#endif

    if (tid < TOPK) {
        const int c = g_topk_idx[tid];
        sidx_tmp[tid] = c;
        sline[tid] = c & ~31;
        ssrc[tid]  = c & 31;
    }
    __syncthreads();

    for (int t = tid; t < TOPK * H1; t += MLP_BLK)
        sW1[t] = W1[(long)sidx_tmp[t >> 5] * H1 + (t & 31)];
    __syncthreads();

    const int row0 = (blockIdx.x * 8 + warp) * RW;

#pragma unroll
    for (int rr = 0; rr < RW; rr++) {
        const int row = row0 + rr;
        const float* __restrict__ xr = x + (long)row * IN_DIM + lane;

        // rotating prefetch: fill 16 lines
        float buf[PF];
#pragma unroll
        for (int k = 0; k < PF; k++)
            buf[k] = __ldg(xr + sline[k]);

        // layer 1: lane owns output j = lane; consume k, prefetch k+16
        float p = sb1[lane];
#pragma unroll
        for (int k = 0; k < TOPK; k++) {
            const float v = __shfl_sync(0xffffffffu, buf[k & (PF - 1)], ssrc[k]);
            if (k + PF < TOPK)
                buf[k & (PF - 1)] = __ldg(xr + sline[k + PF]);
            p = fmaf(v, sW1[k * H1 + lane], p);
        }
        const float a1 = fmaxf(p, 0.0f);

        // layer 2: lane computes output (lane & 15); halves duplicate
        const int j2 = lane & 15;
        float s2 = sb2[j2];
#pragma unroll
        for (int i = 0; i < H1; i++) {
            const float v = __shfl_sync(0xffffffffu, a1, i);
            s2 = fmaf(v, sW2[i * H2 + j2], s2);
        }
        const float a2 = fmaxf(s2, 0.0f);

        // layer 3: lane j < 30 computes output j
        float o = (lane < OUT_DIM) ? sb3[lane] : 0.0f;
#pragma unroll
        for (int i = 0; i < H2; i++) {
            const float v = __shfl_sync(0xffffffffu, a2, i);
            if (lane < OUT_DIM)
                o = fmaf(v, sW3[i * OUT_DIM + lane], o);
        }
        if (lane < OUT_DIM)
            out[(long)row * OUT_DIM + lane] = o;   // 120B contiguous / warp
    }
}

// ---------------------------------------------------------------------------
extern "C" void kernel_launch(void* const* d_in, const int* in_sizes, int n_in,
                              void* d_out, int out_size) {
    const float* x      = (const float*)d_in[0];
    const float* logits = (const float*)d_in[1];
    const float* W1     = (const float*)d_in[2];
    const float* b1     = (const float*)d_in[3];
    const float* W2     = (const float*)d_in[4];
    const float* b2     = (const float*)d_in[5];
    const float* W3     = (const float*)d_in[6];
    const float* b3     = (const float*)d_in[7];

    float* out  = (float*)d_out;
    float* mask = nullptr;
    if (out_size >= BATCH * OUT_DIM + IN_DIM)
        mask = out + (long)BATCH * OUT_DIM;   // tuple order: (out, mask)

    k_topk<<<1, 1024>>>(logits, mask);

    // PDL launch: k_mlp overlaps k_topk; syncs before reading g_topk_idx.
    cudaLaunchConfig_t cfg = {};
    cfg.gridDim  = dim3(MLP_GRID);
    cfg.blockDim = dim3(MLP_BLK);
    cfg.dynamicSmemBytes = 0;
    cfg.stream = 0;
    cudaLaunchAttribute attrs[1];
    attrs[0].id = cudaLaunchAttributeProgrammaticStreamSerialization;
    attrs[0].val.programmaticStreamSerializationAllowed = 1;
    cfg.attrs = attrs;
    cfg.numAttrs = 1;
    cudaError_t err = cudaLaunchKernelEx(&cfg, k_mlp, x, W1, b1, W2, b2, W3, b3, out);
    if (err != cudaSuccess) {
        k_mlp<<<MLP_GRID, MLP_BLK>>>(x, W1, b1, W2, b2, W3, b3, out);
    }
}

// round 12
// speedup vs baseline: 1.0738x; 1.0738x over previous
#include <cuda_runtime.h>
#include <cstdint>

#define IN_DIM   5000
#define TOPK     50
#define BATCH    16384
#define H1       32
#define H2       16
#define OUT_DIM  30

#define NBIN     4096
#define MAXCAND  512

#define RW        2                      // rows per warp, loads prefetched
#define MLP_BLK   256                    // 8 warps -> 16 rows per CTA
#define MLP_GRID  (BATCH / (8 * RW))     // 1024 CTAs

// scratch (no allocations allowed)
__device__ int g_topk_idx[64];

static __device__ __forceinline__ unsigned key32(float f) {
    unsigned u = __float_as_uint(f);
    return (u & 0x80000000u) ? ~u : (u | 0x80000000u);  // monotonic
}

// ---------------------------------------------------------------------------
// Kernel 1: single-CTA histogram top-k -> mask + compact index list
// ---------------------------------------------------------------------------
__global__ void __launch_bounds__(1024, 1)
k_topk(const float* __restrict__ logits, float* __restrict__ mask_out) {
    __shared__ unsigned skey[IN_DIM];
    __shared__ int hist[NBIN];
    __shared__ int groupsum[128];
    __shared__ int sgrp[128];
    __shared__ int sbin[32];
    __shared__ int s_g, s_above, s_T, s_m, s_ncand;
    __shared__ int      cand_idx[MAXCAND];
    __shared__ unsigned cand_key[MAXCAND];
    __shared__ unsigned char sel[IN_DIM];
    __shared__ int wcnt[32], wbase[32];

    const int tid = threadIdx.x;
    const int w = tid >> 5, l = tid & 31;

    for (int i = tid; i < NBIN; i += 1024) hist[i] = 0;
    if (tid == 0) s_ncand = 0;
    __syncthreads();

    for (int i = tid; i < IN_DIM; i += 1024) {
        unsigned u = key32(logits[i]);
        skey[i] = u;
        atomicAdd(&hist[u >> 20], 1);
    }
    __syncthreads();

    if (tid < 128) {
        int s = 0;
#pragma unroll
        for (int j = 0; j < 32; j++) s += hist[tid * 32 + j];
        groupsum[tid] = s;
    }
    __syncthreads();
    if (tid < 128) {
        int s = 0;
        for (int g = tid; g < 128; g++) s += groupsum[g];
        sgrp[tid] = s;
    }
    __syncthreads();
    if (tid < 128) {
        const int nxt = (tid == 127) ? 0 : sgrp[tid + 1];
        if (sgrp[tid] >= TOPK && nxt < TOPK) { s_g = tid; s_above = nxt; }
    }
    __syncthreads();
    if (tid < 32) {
        const int b0 = s_g * 32;
        int s = 0;
        for (int b = b0 + tid; b < b0 + 32; b++) s += hist[b];
        sbin[tid] = s;
    }
    __syncthreads();
    if (tid < 32) {
        const int cur = sbin[tid] + s_above;
        const int nxt = (tid == 31) ? s_above : (sbin[tid + 1] + s_above);
        if (cur >= TOPK && nxt < TOPK) { s_T = s_g * 32 + tid; s_m = TOPK - nxt; }
    }
    __syncthreads();
    const int T = s_T, m = s_m;

    for (int i = tid; i < IN_DIM; i += 1024) {
        const int b = (int)(skey[i] >> 20);
        sel[i] = (b > T) ? 1 : 0;
        if (b == T) {
            int c = atomicAdd(&s_ncand, 1);
            if (c < MAXCAND) { cand_idx[c] = i; cand_key[c] = skey[i]; }
        }
    }
    __syncthreads();

    const int nc = min(s_ncand, MAXCAND);
    for (int ci = tid; ci < nc; ci += 1024) {
        const unsigned ki = cand_key[ci];
        const int      ii = cand_idx[ci];
        int rank = 0;
        for (int cj = 0; cj < nc; cj++) {
            const unsigned kj = cand_key[cj];
            rank += (kj > ki || (kj == ki && cand_idx[cj] < ii)) ? 1 : 0;
        }
        if (rank < m) sel[ii] = 1;
    }
    __syncthreads();

    if (mask_out)
        for (int i = tid; i < IN_DIM; i += 1024)
            mask_out[i] = sel[i] ? 1.0f : 0.0f;

    // parallel index-ordered compaction
    unsigned bm[5];
    int cnt = 0;
#pragma unroll
    for (int c = 0; c < 5; c++) {
        const int i = w * 160 + c * 32 + l;
        const bool s = (i < IN_DIM) && sel[i];
        bm[c] = __ballot_sync(0xffffffffu, s);
        cnt += __popc(bm[c]);
    }
    if (l == 0) wcnt[w] = cnt;
    __syncthreads();
    if (tid < 32) {
        int v = wcnt[tid];
        int inc = v;
#pragma unroll
        for (int d = 1; d < 32; d <<= 1) {
            int t = __shfl_up_sync(0xffffffffu, inc, d);
            if (tid >= d) inc += t;
        }
        wbase[tid] = inc - v;
    }
    __syncthreads();
    int base = wbase[w];
#pragma unroll
    for (int c = 0; c < 5; c++) {
        const int i = w * 160 + c * 32 + l;
        const unsigned b = bm[c];
        if ((i < IN_DIM) && sel[i])
            g_topk_idx[base + __popc(b & ((1u << l) - 1u))] = i;
        base += __popc(b);
    }
}

// ---------------------------------------------------------------------------
// Kernel 2: sector-coalesced warp-per-row gather (13 LDGs/row, 4 sectors per
//   LDG), 2 rows prefetched per warp. CHANGES vs best: x gathers issue BEFORE
//   W1 staging (critical path first), occupancy pushed to 4 CTAs/SM.
//   PDL hides k_topk behind topk-independent weight staging.
// ---------------------------------------------------------------------------
__global__ void __launch_bounds__(MLP_BLK, 4)
k_mlp(const float* __restrict__ x,
      const float* __restrict__ W1, const float* __restrict__ b1,
      const float* __restrict__ W2, const float* __restrict__ b2,
      const float* __restrict__ W3, const float* __restrict__ b3,
      float* __restrict__ out) {
    __shared__ int   ssec[52];        // sector base (col & ~7), padded
    __shared__ int   ssrc[52];        // shfl source lane: ((k&3)<<3) | (col&7)
    __shared__ float sW1[TOPK * H1];  // [k][j]
    __shared__ float sW2[H1 * H2];
    __shared__ float sW3[H2 * OUT_DIM];
    __shared__ float sb1[H1], sb2[H2], sb3[OUT_DIM];
    __shared__ int   sidx_tmp[TOPK];

    const int tid  = threadIdx.x;
    const int warp = tid >> 5;
    const int lane = tid & 31;

    // ---- stage topk-independent weights while k_topk still runs (PDL) ----
    for (int t = tid; t < H1 * H2; t += MLP_BLK)      sW2[t] = W2[t];
    for (int t = tid; t < H2 * OUT_DIM; t += MLP_BLK) sW3[t] = W3[t];
    if (tid < H1)      sb1[tid] = b1[tid];
    if (tid < H2)      sb2[tid] = b2[tid];
    if (tid < OUT_DIM) sb3[tid] = b3[tid];

#if __CUDA_ARCH__ >= 900
    cudaGridDependencySynchronize();
#endif

    if (tid < TOPK) {
        const int c = g_topk_idx[tid];
        sidx_tmp[tid] = c;
        ssec[tid] = c & ~7;
        ssrc[tid] = ((tid & 3) << 3) | (c & 7);
    }
    if (tid >= TOPK && tid < 52) { ssec[tid] = 0; ssrc[tid] = 0; }
    __syncthreads();

    // lane's fixed per-row offsets: group g loads k = 4g + (lane>>3),
    // in-sector offset (lane&7)
    int myoff[13];
#pragma unroll
    for (int g = 0; g < 13; g++)
        myoff[g] = ssec[4 * g + (lane >> 3)] + (lane & 7);

    const int row0 = (blockIdx.x * 8 + warp) * RW;

    // ---- CRITICAL PATH FIRST: issue both rows' 13 sector-gather LDGs ----
    float lv[RW][13];
#pragma unroll
    for (int rr = 0; rr < RW; rr++) {
        const float* __restrict__ xr = x + (long)(row0 + rr) * IN_DIM;
#pragma unroll
        for (int g = 0; g < 13; g++)
            lv[rr][g] = __ldg(xr + myoff[g]);
    }

    // ---- W1 staging overlaps the gather flight ----
    for (int t = tid; t < TOPK * H1; t += MLP_BLK)
        sW1[t] = W1[(long)sidx_tmp[t >> 5] * H1 + (t & 31)];
    __syncthreads();

#pragma unroll
    for (int rr = 0; rr < RW; rr++) {
        const int row = row0 + rr;

        // layer 1: lane owns output j = lane
        float p = sb1[lane];
#pragma unroll
        for (int k = 0; k < TOPK; k++) {
            const float v = __shfl_sync(0xffffffffu, lv[rr][k >> 2], ssrc[k]);
            p = fmaf(v, sW1[k * H1 + lane], p);
        }
        const float a1 = fmaxf(p, 0.0f);

        // layer 2: lane computes output (lane & 15); halves duplicate
        const int j2 = lane & 15;
        float s2 = sb2[j2];
#pragma unroll
        for (int i = 0; i < H1; i++) {
            const float v = __shfl_sync(0xffffffffu, a1, i);
            s2 = fmaf(v, sW2[i * H2 + j2], s2);
        }
        const float a2 = fmaxf(s2, 0.0f);

        // layer 3: lane j < 30 computes output j
        float o = (lane < OUT_DIM) ? sb3[lane] : 0.0f;
#pragma unroll
        for (int i = 0; i < H2; i++) {
            const float v = __shfl_sync(0xffffffffu, a2, i);
            if (lane < OUT_DIM)
                o = fmaf(v, sW3[i * OUT_DIM + lane], o);
        }
        if (lane < OUT_DIM)
            out[(long)row * OUT_DIM + lane] = o;   // 120B contiguous / warp
    }
}

// ---------------------------------------------------------------------------
extern "C" void kernel_launch(void* const* d_in, const int* in_sizes, int n_in,
                              void* d_out, int out_size) {
    const float* x      = (const float*)d_in[0];
    const float* logits = (const float*)d_in[1];
    const float* W1     = (const float*)d_in[2];
    const float* b1     = (const float*)d_in[3];
    const float* W2     = (const float*)d_in[4];
    const float* b2     = (const float*)d_in[5];
    const float* W3     = (const float*)d_in[6];
    const float* b3     = (const float*)d_in[7];

    float* out  = (float*)d_out;
    float* mask = nullptr;
    if (out_size >= BATCH * OUT_DIM + IN_DIM)
        mask = out + (long)BATCH * OUT_DIM;   // tuple order: (out, mask)

    k_topk<<<1, 1024>>>(logits, mask);

    // PDL launch: k_mlp overlaps k_topk; syncs before reading g_topk_idx.
    cudaLaunchConfig_t cfg = {};
    cfg.gridDim  = dim3(MLP_GRID);
    cfg.blockDim = dim3(MLP_BLK);
    cfg.dynamicSmemBytes = 0;
    cfg.stream = 0;
    cudaLaunchAttribute attrs[1];
    attrs[0].id = cudaLaunchAttributeProgrammaticStreamSerialization;
    attrs[0].val.programmaticStreamSerializationAllowed = 1;
    cfg.attrs = attrs;
    cfg.numAttrs = 1;
    cudaError_t err = cudaLaunchKernelEx(&cfg, k_mlp, x, W1, b1, W2, b2, W3, b3, out);
    if (err != cudaSuccess) {
        k_mlp<<<MLP_GRID, MLP_BLK>>>(x, W1, b1, W2, b2, W3, b3, out);
    }
}

// round 13
// speedup vs baseline: 1.6619x; 1.5477x over previous
#include <cuda_runtime.h>
#include <cstdint>

#define IN_DIM   5000
#define TOPK     50
#define BATCH    16384
#define H1       32
#define H2       16
#define OUT_DIM  30

#define NBIN     4096
#define MAXCAND  512

#define RW        2                      // rows per warp, loads prefetched
#define MLP_BLK   256                    // 8 warps -> 16 rows per CTA
#define MLP_GRID  (BATCH / (8 * RW))     // 1024 CTAs

// scratch (no allocations allowed)
__device__ int g_topk_idx[64];

static __device__ __forceinline__ unsigned key32(float f) {
    unsigned u = __float_as_uint(f);
    return (u & 0x80000000u) ? ~u : (u | 0x80000000u);  // monotonic
}

// ---------------------------------------------------------------------------
// Kernel 1: single-CTA histogram top-k -> mask + compact index list.
// Slimmed: per-thread keys live in registers across both passes (no skey
// smem array, no re-keying pass).
// ---------------------------------------------------------------------------
__global__ void __launch_bounds__(1024, 1)
k_topk(const float* __restrict__ logits, float* __restrict__ mask_out) {
    __shared__ int hist[NBIN];
    __shared__ int groupsum[128];
    __shared__ int sgrp[128];
    __shared__ int sbin[32];
    __shared__ int s_g, s_above, s_T, s_m, s_ncand;
    __shared__ int      cand_idx[MAXCAND];
    __shared__ unsigned cand_key[MAXCAND];
    __shared__ unsigned char sel[IN_DIM];
    __shared__ int wcnt[32], wbase[32];

    const int tid = threadIdx.x;
    const int w = tid >> 5, l = tid & 31;

    for (int i = tid; i < NBIN; i += 1024) hist[i] = 0;
    if (tid == 0) s_ncand = 0;
    __syncthreads();

    // pass 1: keys (kept in registers) + 12-bit histogram
    unsigned myu[5];
#pragma unroll
    for (int c = 0; c < 5; c++) {
        const int i = tid + c * 1024;
        if (i < IN_DIM) {
            const unsigned u = key32(logits[i]);
            myu[c] = u;
            atomicAdd(&hist[u >> 20], 1);
        } else {
            myu[c] = 0u;
        }
    }
    __syncthreads();

    // group sums (128 groups of 32 bins), parallel suffix sums
    if (tid < 128) {
        int s = 0;
#pragma unroll
        for (int j = 0; j < 32; j++) s += hist[tid * 32 + j];
        groupsum[tid] = s;
    }
    __syncthreads();
    if (tid < 128) {
        int s = 0;
        for (int g = tid; g < 128; g++) s += groupsum[g];
        sgrp[tid] = s;
    }
    __syncthreads();
    if (tid < 128) {
        const int nxt = (tid == 127) ? 0 : sgrp[tid + 1];
        if (sgrp[tid] >= TOPK && nxt < TOPK) { s_g = tid; s_above = nxt; }
    }
    __syncthreads();
    if (tid < 32) {
        const int b0 = s_g * 32;
        int s = 0;
        for (int b = b0 + tid; b < b0 + 32; b++) s += hist[b];
        sbin[tid] = s;
    }
    __syncthreads();
    if (tid < 32) {
        const int cur = sbin[tid] + s_above;
        const int nxt = (tid == 31) ? s_above : (sbin[tid + 1] + s_above);
        if (cur >= TOPK && nxt < TOPK) { s_T = s_g * 32 + tid; s_m = TOPK - nxt; }
    }
    __syncthreads();
    const int T = s_T, m = s_m;

    // pass 2: classify from register keys; collect threshold-bin candidates
#pragma unroll
    for (int c = 0; c < 5; c++) {
        const int i = tid + c * 1024;
        if (i < IN_DIM) {
            const int b = (int)(myu[c] >> 20);
            sel[i] = (b > T) ? 1 : 0;
            if (b == T) {
                int cc = atomicAdd(&s_ncand, 1);
                if (cc < MAXCAND) { cand_idx[cc] = i; cand_key[cc] = myu[c]; }
            }
        }
    }
    __syncthreads();

    // exact rank among candidates (~20-30); tie -> lower index wins
    const int nc = min(s_ncand, MAXCAND);
    for (int ci = tid; ci < nc; ci += 1024) {
        const unsigned ki = cand_key[ci];
        const int      ii = cand_idx[ci];
        int rank = 0;
        for (int cj = 0; cj < nc; cj++) {
            const unsigned kj = cand_key[cj];
            rank += (kj > ki || (kj == ki && cand_idx[cj] < ii)) ? 1 : 0;
        }
        if (rank < m) sel[ii] = 1;
    }
    __syncthreads();

    // mask output
    if (mask_out) {
#pragma unroll
        for (int c = 0; c < 5; c++) {
            const int i = tid + c * 1024;
            if (i < IN_DIM) mask_out[i] = sel[i] ? 1.0f : 0.0f;
        }
    }

    // parallel index-ordered compaction: warp w covers [w*160, w*160+160)
    unsigned bm[5];
    int cnt = 0;
#pragma unroll
    for (int c = 0; c < 5; c++) {
        const int i = w * 160 + c * 32 + l;
        const bool s = (i < IN_DIM) && sel[i];
        bm[c] = __ballot_sync(0xffffffffu, s);
        cnt += __popc(bm[c]);
    }
    if (l == 0) wcnt[w] = cnt;
    __syncthreads();
    if (tid < 32) {
        int v = wcnt[tid];
        int inc = v;
#pragma unroll
        for (int d = 1; d < 32; d <<= 1) {
            int t = __shfl_up_sync(0xffffffffu, inc, d);
            if (tid >= d) inc += t;
        }
        wbase[tid] = inc - v;
    }
    __syncthreads();
    int base = wbase[w];
#pragma unroll
    for (int c = 0; c < 5; c++) {
        const int i = w * 160 + c * 32 + l;
        const unsigned b = bm[c];
        if ((i < IN_DIM) && sel[i])
            g_topk_idx[base + __popc(b & ((1u << l) - 1u))] = i;
        base += __popc(b);
    }
}

// ---------------------------------------------------------------------------
// Kernel 2: sector-coalesced warp-per-row gather (13 LDGs cover a row's 50
//   columns; 4 sectors per LDG) with 2 rows prefetched per warp, grid 1024.
//   EXACT R10 structure (twice-validated best). PDL hides k_topk.
// ---------------------------------------------------------------------------
__global__ void __launch_bounds__(MLP_BLK, 3)
k_mlp(const float* __restrict__ x,
      const float* __restrict__ W1, const float* __restrict__ b1,
      const float* __restrict__ W2, const float* __restrict__ b2,
      const float* __restrict__ W3, const float* __restrict__ b3,
      float* __restrict__ out) {
    __shared__ int   ssec[52];        // sector base (col & ~7), padded
    __shared__ int   ssrc[52];        // shfl source lane: ((k&3)<<3) | (col&7)
    __shared__ float sW1[TOPK * H1];  // [k][j]
    __shared__ float sW2[H1 * H2];
    __shared__ float sW3[H2 * OUT_DIM];
    __shared__ float sb1[H1], sb2[H2], sb3[OUT_DIM];
    __shared__ int   sidx_tmp[TOPK];

    const int tid  = threadIdx.x;
    const int warp = tid >> 5;
    const int lane = tid & 31;

    // ---- stage topk-independent weights while k_topk may still run (PDL) ----
    for (int t = tid; t < H1 * H2; t += MLP_BLK)      sW2[t] = W2[t];
    for (int t = tid; t < H2 * OUT_DIM; t += MLP_BLK) sW3[t] = W3[t];
    if (tid < H1)      sb1[tid] = b1[tid];
    if (tid < H2)      sb2[tid] = b2[tid];
    if (tid < OUT_DIM) sb3[tid] = b3[tid];

#if __CUDA_ARCH__ >= 900
    cudaGridDependencySynchronize();
#endif

    if (tid < TOPK) {
        const int c = g_topk_idx[tid];
        sidx_tmp[tid] = c;
        ssec[tid] = c & ~7;
        ssrc[tid] = ((tid & 3) << 3) | (c & 7);
    }
    if (tid >= TOPK && tid < 52) { ssec[tid] = 0; ssrc[tid] = 0; }
    __syncthreads();

    for (int t = tid; t < TOPK * H1; t += MLP_BLK)
        sW1[t] = W1[(long)sidx_tmp[t >> 5] * H1 + (t & 31)];

    // lane's fixed per-row offsets: group g loads k = 4g + (lane>>3),
    // in-sector offset (lane&7)
    int myoff[13];
#pragma unroll
    for (int g = 0; g < 13; g++)
        myoff[g] = ssec[4 * g + (lane >> 3)] + (lane & 7);

    const int row0 = (blockIdx.x * 8 + warp) * RW;

    // prefetch BOTH rows' 13 sector-gather LDGs (26 in flight per warp)
    float lv[RW][13];
#pragma unroll
    for (int rr = 0; rr < RW; rr++) {
        const float* __restrict__ xr = x + (long)(row0 + rr) * IN_DIM;
#pragma unroll
        for (int g = 0; g < 13; g++)
            lv[rr][g] = __ldg(xr + myoff[g]);
    }

    __syncthreads();   // sW1 ready

#pragma unroll
    for (int rr = 0; rr < RW; rr++) {
        const int row = row0 + rr;

        // layer 1: lane owns output j = lane
        float p = sb1[lane];
#pragma unroll
        for (int k = 0; k < TOPK; k++) {
            const float v = __shfl_sync(0xffffffffu, lv[rr][k >> 2], ssrc[k]);
            p = fmaf(v, sW1[k * H1 + lane], p);
        }
        const float a1 = fmaxf(p, 0.0f);

        // layer 2: lane computes output (lane & 15); halves duplicate
        const int j2 = lane & 15;
        float s2 = sb2[j2];
#pragma unroll
        for (int i = 0; i < H1; i++) {
            const float v = __shfl_sync(0xffffffffu, a1, i);
            s2 = fmaf(v, sW2[i * H2 + j2], s2);
        }
        const float a2 = fmaxf(s2, 0.0f);

        // layer 3: lane j < 30 computes output j
        float o = (lane < OUT_DIM) ? sb3[lane] : 0.0f;
#pragma unroll
        for (int i = 0; i < H2; i++) {
            const float v = __shfl_sync(0xffffffffu, a2, i);
            if (lane < OUT_DIM)
                o = fmaf(v, sW3[i * OUT_DIM + lane], o);
        }
        if (lane < OUT_DIM)
            out[(long)row * OUT_DIM + lane] = o;   // 120B contiguous / warp
    }
}

// ---------------------------------------------------------------------------
extern "C" void kernel_launch(void* const* d_in, const int* in_sizes, int n_in,
                              void* d_out, int out_size) {
    const float* x      = (const float*)d_in[0];
    const float* logits = (const float*)d_in[1];
    const float* W1     = (const float*)d_in[2];
    const float* b1     = (const float*)d_in[3];
    const float* W2     = (const float*)d_in[4];
    const float* b2     = (const float*)d_in[5];
    const float* W3     = (const float*)d_in[6];
    const float* b3     = (const float*)d_in[7];

    float* out  = (float*)d_out;
    float* mask = nullptr;
    if (out_size >= BATCH * OUT_DIM + IN_DIM)
        mask = out + (long)BATCH * OUT_DIM;   // tuple order: (out, mask)

    k_topk<<<1, 1024>>>(logits, mask);

    // PDL launch: k_mlp overlaps k_topk; syncs before reading g_topk_idx.
    cudaLaunchConfig_t cfg = {};
    cfg.gridDim  = dim3(MLP_GRID);
    cfg.blockDim = dim3(MLP_BLK);
    cfg.dynamicSmemBytes = 0;
    cfg.stream = 0;
    cudaLaunchAttribute attrs[1];
    attrs[0].id = cudaLaunchAttributeProgrammaticStreamSerialization;
    attrs[0].val.programmaticStreamSerializationAllowed = 1;
    cfg.attrs = attrs;
    cfg.numAttrs = 1;
    cudaError_t err = cudaLaunchKernelEx(&cfg, k_mlp, x, W1, b1, W2, b2, W3, b3, out);
    if (err != cudaSuccess) {
        k_mlp<<<MLP_GRID, MLP_BLK>>>(x, W1, b1, W2, b2, W3, b3, out);
    }
}